// round 6
// baseline (speedup 1.0000x reference)
#include <cuda_runtime.h>
#include <cuda_bf16.h>
#include <cstdint>
#include <cstddef>

// ============================================================================
// TripletSTDP: B=32, T=512, N_PRE=N_POST=1024.
// wu = (1/16384) * [ (R @ post^T)      -- LTP, K=16384
//                  - (pre @ O^T) ]     -- LTD, K=16384
// All four operand matrices are quantized to u8 with per-tensor scales and
// stored PRE-PERMUTED in mma.m16n8k32 fragment order. Two u8 IMMA GEMMs with
// exact s32 accumulation; signs/scales applied in the final reduce.
//   scale_spike = 255   (values in [0,1))
//   scale_R     = 819   (R <= 0.31064)
//   scale_O     = 744   (O <= 0.34244)
// ============================================================================

static __device__ __align__(128) uint8_t g_Altp[1024ull * 16384ull]; // R traces   (A layout)
static __device__ __align__(128) uint8_t g_Altd[1024ull * 16384ull]; // pre spikes (A layout)
static __device__ __align__(128) uint8_t g_Bltp[1024ull * 16384ull]; // post spikes(B layout)
static __device__ __align__(128) uint8_t g_Bltd[1024ull * 16384ull]; // O traces   (B layout)
static __device__ __align__(128) int     g_WSi[8ull * 1024ull * 1024ull]; // [h*4+kz][1M] s32

constexpr float SCALE_SP = 255.0f;
constexpr float SCALE_R  = 819.0f;   // 0.31064*819 = 254.4 < 255.5
constexpr float SCALE_O  = 744.0f;   // 0.34244*744 = 254.8 < 255.5

// ---------------------------------------------------------------------------
__device__ __forceinline__ void mma_u8(int* d, const uint32_t* a,
                                       uint32_t b0, uint32_t b1) {
    asm volatile(
        "mma.sync.aligned.m16n8k32.row.col.s32.u8.u8.s32 "
        "{%0,%1,%2,%3}, {%4,%5,%6,%7}, {%8,%9}, {%0,%1,%2,%3};"
        : "+r"(d[0]), "+r"(d[1]), "+r"(d[2]), "+r"(d[3])
        : "r"(a[0]), "r"(a[1]), "r"(a[2]), "r"(a[3]), "r"(b0), "r"(b1));
}
__device__ __forceinline__ uint32_t smem_u32(const void* p) {
    uint32_t a;
    asm("{ .reg .u64 t; cvta.to.shared.u64 t, %1; cvt.u32.u64 %0, t; }" : "=r"(a) : "l"(p));
    return a;
}
__device__ __forceinline__ void cp16(uint32_t dst, const void* src) {
    asm volatile("cp.async.cg.shared.global [%0], [%1], 16;" :: "r"(dst), "l"(src));
}

// ---------------------------------------------------------------------------
// Kernel 1: trace scan + u8 quantize + fragment-layout store.
// grid (8 p-tiles, 32 batch, 2 sides), 128 threads.
// Fragment layouts for m16n8k32 (16B per lane slot):
//  A slot: d16 = ((mt*512 + ks32)*8 + mfrag)*32 + lane
//    .x=a0: A[m0][k0..k0+3]  .y=a1: m0+8  .z=a2: k0+16  .w=a3: m0+8,k0+16
//    m0 = mfrag*16 + (lane>>2), k0 = ks32*32 + (lane&3)*4
//  B slot: d16 = ((nt*512 + ks32)*16 + n16)*32 + lane
//    .x=b0(even n8) .y=b0(odd n8) .z=b1(even) .w=b1(odd)
//    n_even = n16*16 + (lane>>2), n_odd = +8; b0: k0..k0+3, b1: k0+16..k0+19
// ---------------------------------------------------------------------------
__global__ void __launch_bounds__(128) stdp_scan_kernel(const float* __restrict__ pre,
                                                        const float* __restrict__ post)
{
    const int side = blockIdx.z;                 // 0: pre side, 1: post side
    const float* __restrict__ in = side ? post : pre;
    const int b   = blockIdx.y;
    const int bx  = blockIdx.x;
    const int tid = threadIdx.x;
    const int p0  = bx * 128;

    const float dA  = 0.95122942f;                      // exp(-1/20)
    const float dB  = side ? 0.99126643f : 0.99014786f; // exp(-1/114) / exp(-1/101)
    const float c1  = side ? 0.00525f : 0.005f;         // A_MINUS / A_PLUS
    const float c2  = 0.0001f;
    const float str = side ? SCALE_O : SCALE_R;

    __shared__ __align__(4) uint8_t s_tr[128][68];
    __shared__ __align__(4) uint8_t s_sp[128][68];

    float t1 = 0.f, t2 = 0.f;
    const float* src = in + (size_t)b * (512 * 1024) + p0 + tid;

    for (int ch = 0; ch < 8; ++ch) {
        #pragma unroll
        for (int tt = 0; tt < 64; ++tt) {
            float x = src[(size_t)(ch * 64 + tt) * 1024];
            t1 *= dA; t2 *= dB;                          // decay first
            float tr = fmaf(c2 * t1, t2, c1 * t1);       // c1*r1 + c2*r1*r2
            s_tr[tid][tt] = (uint8_t)__float2uint_rn(tr * str);
            s_sp[tid][tt] = (uint8_t)__float2uint_rn(x * SCALE_SP);
            t1 += x; t2 += x;                            // then add spike
        }
        __syncthreads();
        const int ksb = b * 16 + ch * 2;                 // global ks32 base of chunk
        #pragma unroll
        for (int it = 0; it < 4; ++it) {
            int f    = it * 128 + tid;                   // slot id 0..511
            int lane = f & 31;
            int ksl  = (f >> 5) & 1;
            int frag = f >> 6;                           // 0..7
            int g    = lane >> 2, t4 = lane & 3;
            int pr   = frag * 16 + g;
            int tb   = ksl * 32 + t4 * 4;
            uint4 wt, ws;
            wt.x = *(const uint32_t*)&s_tr[pr    ][tb     ];
            wt.y = *(const uint32_t*)&s_tr[pr + 8][tb     ];
            wt.z = *(const uint32_t*)&s_tr[pr    ][tb + 16];
            wt.w = *(const uint32_t*)&s_tr[pr + 8][tb + 16];
            ws.x = *(const uint32_t*)&s_sp[pr    ][tb     ];
            ws.y = *(const uint32_t*)&s_sp[pr + 8][tb     ];
            ws.z = *(const uint32_t*)&s_sp[pr    ][tb + 16];
            ws.w = *(const uint32_t*)&s_sp[pr + 8][tb + 16];
            int ks32 = ksb + ksl;
            if (side == 0) {   // A layout: traces->Altp, spikes->Altd
                size_t d16 = ((size_t)(bx * 512 + ks32) * 8 + frag) * 32 + lane;
                reinterpret_cast<uint4*>(g_Altp)[d16] = wt;
                reinterpret_cast<uint4*>(g_Altd)[d16] = ws;
            } else {           // B layout: spikes->Bltp, traces->Bltd
                size_t d16 = ((size_t)((bx >> 1) * 512 + ks32) * 16
                              + (bx & 1) * 8 + frag) * 32 + lane;
                reinterpret_cast<uint4*>(g_Bltp)[d16] = ws;
                reinterpret_cast<uint4*>(g_Bltd)[d16] = wt;
            }
        }
        __syncthreads();
    }
}

// ---------------------------------------------------------------------------
// Kernel 2: u8 IMMA GEMM x2 (LTP then LTD). CTA 128x256, 8 warps (2Mx4N),
// warp tile 64x64, split-K=4 -> grid(8,4,4). 4-stage cp.async pipeline of
// k128 chunks (A 16KB + B 32KB); register fragment prefetch across barriers.
// ---------------------------------------------------------------------------
constexpr int      GEMM_STAGES = 4;
constexpr int      CHUNK_U4    = 3072;                        // 1024 A + 2048 B uint4
constexpr uint32_t GEMM_SMEM_B = GEMM_STAGES * CHUNK_U4 * 16; // 196608 B

__global__ void __launch_bounds__(256, 1) stdp_gemm_kernel()
{
    extern __shared__ __align__(16) uint4 sm[];               // [4][3072]
    const int tid  = threadIdx.x;
    const int lane = tid & 31;
    const int wid  = tid >> 5;
    const int wm   = wid & 1;
    const int wn   = wid >> 1;
    const int mt   = blockIdx.x;
    const int nt   = blockIdx.y;
    const int kz   = blockIdx.z;

    const uint32_t smb = smem_u32(sm);

    auto fill = [&](const uint4* gA, const uint4* gB, int c, int s) {
        uint32_t stA = smb + (uint32_t)s * (CHUNK_U4 * 16);
        uint32_t stB = stA + 1024 * 16;
        const uint4* srcA = gA + (size_t)c * 1024;
        const uint4* srcB = gB + (size_t)c * 2048;
        #pragma unroll
        for (int i = 0; i < 4; ++i)
            cp16(stA + (uint32_t)(tid + i * 256) * 16, srcA + tid + i * 256);
        #pragma unroll
        for (int i = 0; i < 8; ++i)
            cp16(stB + (uint32_t)(tid + i * 256) * 16, srcB + tid + i * 256);
    };
    auto aAddr = [&](int c, int ksl, int i) -> const uint4* {
        return sm + (c & 3) * CHUNK_U4 + (size_t)(ksl * 8 + wm * 4 + i) * 32 + lane;
    };
    auto bAddr = [&](int c, int ksl, int j) -> const uint4* {
        return sm + (c & 3) * CHUNK_U4 + 1024 + (size_t)(ksl * 16 + wn * 4 + j) * 32 + lane;
    };

    const int gid = lane >> 2, tig = lane & 3;

    #pragma unroll 1
    for (int h = 0; h < 2; ++h) {
        const uint4* gA = reinterpret_cast<const uint4*>(h ? g_Altd : g_Altp)
                        + (size_t)(mt * 512 + kz * 128) * 256;
        const uint4* gB = reinterpret_cast<const uint4*>(h ? g_Bltd : g_Bltp)
                        + (size_t)(nt * 512 + kz * 128) * 512;

        int acc[4][8][4];
        #pragma unroll
        for (int i = 0; i < 4; ++i)
            #pragma unroll
            for (int j = 0; j < 8; ++j)
                #pragma unroll
                for (int c = 0; c < 4; ++c) acc[i][j][c] = 0;

        #pragma unroll
        for (int f = 0; f < 3; ++f) {
            fill(gA, gB, f, f);
            asm volatile("cp.async.commit_group;" ::: "memory");
        }
        asm volatile("cp.async.wait_group 1;" ::: "memory");
        __syncthreads();

        uint4 af[2][4], bf[2][4];
        #pragma unroll
        for (int i = 0; i < 4; ++i) af[0][i] = *aAddr(0, 0, i);
        #pragma unroll
        for (int j = 0; j < 4; ++j) bf[0][j] = *bAddr(0, 0, j);

        for (int c = 0; c < 32; ++c) {
            #pragma unroll
            for (int ksl = 0; ksl < 4; ++ksl) {
                const int cur = ksl & 1;
                const int nxt = cur ^ 1;
                const int pc  = (ksl == 3) ? (c + 1) : c;  // c+1 resident (wait_group 1);
                const int pk  = (ksl + 1) & 3;             // c=31 prefetch is dead but safe
                #pragma unroll
                for (int i = 0; i < 4; ++i) af[nxt][i] = *aAddr(pc, pk, i);
                #pragma unroll
                for (int j = 0; j < 4; ++j) bf[nxt][j] = *bAddr(pc, pk, j);
                #pragma unroll
                for (int i = 0; i < 4; ++i) {
                    const uint32_t* a = reinterpret_cast<const uint32_t*>(&af[cur][i]);
                    #pragma unroll
                    for (int j = 0; j < 4; ++j) {
                        mma_u8(acc[i][2 * j + 0], a, bf[cur][j].x, bf[cur][j].z); // even n8
                        mma_u8(acc[i][2 * j + 1], a, bf[cur][j].y, bf[cur][j].w); // odd n8
                    }
                }
            }
            if (c + 3 < 32) fill(gA, gB, c + 3, (c + 3) & 3);
            asm volatile("cp.async.commit_group;" ::: "memory");
            asm volatile("cp.async.wait_group 1;" ::: "memory");
            __syncthreads();
        }

        // epilogue: s32 partial for this (half, kz)
        int* ws = g_WSi + ((size_t)(h * 4 + kz) << 20);
        #pragma unroll
        for (int i = 0; i < 4; ++i) {
            int row0 = mt * 128 + (wm * 4 + i) * 16 + gid;
            #pragma unroll
            for (int j = 0; j < 8; ++j) {
                int col = nt * 256 + (wn * 4 + (j >> 1)) * 16 + (j & 1) * 8 + tig * 2;
                int* d0 = ws + (size_t)row0 * 1024 + col;
                d0[0] = acc[i][j][0];
                d0[1] = acc[i][j][1];
                int* d1 = d0 + 8 * 1024;
                d1[0] = acc[i][j][2];
                d1[1] = acc[i][j][3];
            }
        }
        __syncthreads();   // smem pipeline reuse safety across halves
    }
}

// ---------------------------------------------------------------------------
// Kernel 3: combine split-K + halves, apply scales. Exact int sums.
// ---------------------------------------------------------------------------
__global__ void __launch_bounds__(256) stdp_reduce_kernel(float* __restrict__ out)
{
    int i = blockIdx.x * 256 + threadIdx.x;      // int4 units, 0..262143
    const int4* w = reinterpret_cast<const int4*>(g_WSi);
    int4 p = w[i];
    int4 p1 = w[i + 1 * 262144], p2 = w[i + 2 * 262144], p3 = w[i + 3 * 262144];
    p.x += p1.x + p2.x + p3.x;  p.y += p1.y + p2.y + p3.y;
    p.z += p1.z + p2.z + p3.z;  p.w += p1.w + p2.w + p3.w;
    int4 q = w[i + 4 * 262144];
    int4 q1 = w[i + 5 * 262144], q2 = w[i + 6 * 262144], q3 = w[i + 7 * 262144];
    q.x += q1.x + q2.x + q3.x;  q.y += q1.y + q2.y + q3.y;
    q.z += q1.z + q2.z + q3.z;  q.w += q1.w + q2.w + q3.w;

    const float sP = 1.0f / (SCALE_R * SCALE_SP * 16384.0f);
    const float sQ = 1.0f / (SCALE_O * SCALE_SP * 16384.0f);
    float4 r;
    r.x = (float)p.x * sP - (float)q.x * sQ;
    r.y = (float)p.y * sP - (float)q.y * sQ;
    r.z = (float)p.z * sP - (float)q.z * sQ;
    r.w = (float)p.w * sP - (float)q.w * sQ;
    reinterpret_cast<float4*>(out)[i] = r;
}

// ---------------------------------------------------------------------------
extern "C" void kernel_launch(void* const* d_in, const int* in_sizes, int n_in,
                              void* d_out, int out_size)
{
    (void)in_sizes; (void)n_in; (void)out_size;
    const float* pre  = (const float*)d_in[0];
    const float* post = (const float*)d_in[1];
    float* out = (float*)d_out;

    stdp_scan_kernel<<<dim3(8, 32, 2), 128>>>(pre, post);

    cudaFuncSetAttribute(stdp_gemm_kernel,
                         cudaFuncAttributeMaxDynamicSharedMemorySize, GEMM_SMEM_B);
    stdp_gemm_kernel<<<dim3(8, 4, 4), 256, GEMM_SMEM_B>>>();

    stdp_reduce_kernel<<<1024, 256>>>(out);
}

// round 7
// speedup vs baseline: 2.9129x; 2.9129x over previous
#include <cuda_runtime.h>
#include <cuda_bf16.h>
#include <cstdint>
#include <cstddef>

// ============================================================================
// TripletSTDP: B=32, T=512, N_PRE=N_POST=1024.
// wu = (1/(B*T)) * (A @ B^T), K = 2*B*T = 32768
//   A[m][k]: k<16384 -> R trace of pre (decayed), k>=16384 -> pre spike
//   B[n][k]: k<16384 -> post spike,               k>=16384 -> -O trace of post
// A/B stored PRE-PERMUTED in mma.m16n8k16 fragment order (bf16). GEMM = R5
// (best known: smem 4-stage cp.async + register fragment prefetch).
// Scan now stages input through a cp.async double buffer to keep HBM busy.
// ============================================================================

static __device__ __align__(128) __nv_bfloat16 g_A[1024ull * 32768ull]; // 64 MB
static __device__ __align__(128) __nv_bfloat16 g_B[1024ull * 32768ull]; // 64 MB
static __device__ __align__(128) float         g_WS[4ull * 1024ull * 1024ull]; // split-K partials

// ---------------------------------------------------------------------------
__device__ __forceinline__ void mma_bf16(float* d, const uint32_t* a,
                                         uint32_t b0, uint32_t b1) {
    asm volatile(
        "mma.sync.aligned.m16n8k16.row.col.f32.bf16.bf16.f32 "
        "{%0,%1,%2,%3}, {%4,%5,%6,%7}, {%8,%9}, {%0,%1,%2,%3};"
        : "+f"(d[0]), "+f"(d[1]), "+f"(d[2]), "+f"(d[3])
        : "r"(a[0]), "r"(a[1]), "r"(a[2]), "r"(a[3]), "r"(b0), "r"(b1));
}
__device__ __forceinline__ uint32_t smem_u32(const void* p) {
    uint32_t a;
    asm("{ .reg .u64 t; cvta.to.shared.u64 t, %1; cvt.u32.u64 %0, t; }" : "=r"(a) : "l"(p));
    return a;
}
__device__ __forceinline__ void cp16(uint32_t dst, const void* src) {
    asm volatile("cp.async.cg.shared.global [%0], [%1], 16;" :: "r"(dst), "l"(src));
}

// ---------------------------------------------------------------------------
// Kernel 1: trace scan + fragment-layout store, cp.async-staged input.
// grid (8 p-tiles, 32 batch, 2 sides), 128 threads. 16 chunks of 32 t-steps.
// ---------------------------------------------------------------------------
__global__ void __launch_bounds__(128) stdp_scan_kernel(const float* __restrict__ pre,
                                                        const float* __restrict__ post)
{
    const int side = blockIdx.z;
    const float* __restrict__ in = side ? post : pre;
    __nv_bfloat16* mat = side ? g_B : g_A;
    const int b   = blockIdx.y;
    const int bx  = blockIdx.x;
    const int tid = threadIdx.x;
    const int p0  = bx * 128;

    const float dA = 0.95122942f;                      // exp(-1/20)
    const float dB = side ? 0.99126643f : 0.99014786f; // exp(-1/114) / exp(-1/101)
    const float c1 = side ? 0.00525f : 0.005f;         // A_MINUS / A_PLUS
    const float c2 = 0.0001f;

    __shared__ __align__(16) float         sx[2][32 * 128];   // 2 x 16 KB input stages
    __shared__ __align__(16) __nv_bfloat16 s1[128][40];       // 10 KB (pad 40: 20-word rows,
    __shared__ __align__(16) __nv_bfloat16 s2[128][40];       //  conflict-free transpose reads)

    const float* base = in + (size_t)b * (512 * 1024) + p0;
    const uint32_t sxb = smem_u32(sx);

    // fill chunk ch (32 rows x 512 B) into stage s
    auto fill = [&](int ch, int s) {
        const float* g = base + (size_t)ch * 32 * 1024;
        uint32_t st = sxb + (uint32_t)s * (32 * 128 * 4);
        #pragma unroll
        for (int i = 0; i < 8; ++i) {
            int idx = tid + i * 128;          // 0..1023
            int r = idx >> 5, j = idx & 31;
            cp16(st + (uint32_t)(r * 512 + j * 16), g + (size_t)r * 1024 + j * 4);
        }
    };

    fill(0, 0);
    asm volatile("cp.async.commit_group;" ::: "memory");

    float t1 = 0.f, t2 = 0.f;

    for (int ch = 0; ch < 16; ++ch) {
        asm volatile("cp.async.wait_group 0;" ::: "memory");
        __syncthreads();                       // stage ch&1 visible to all
        if (ch + 1 < 16) fill(ch + 1, (ch + 1) & 1);
        asm volatile("cp.async.commit_group;" ::: "memory");

        const float* x_s = sx[ch & 1];
        #pragma unroll
        for (int tt = 0; tt < 32; ++tt) {
            float x = x_s[tt * 128 + tid];
            t1 *= dA; t2 *= dB;                          // decay first
            float tr = fmaf(c2 * t1, t2, c1 * t1);       // c1*r1 + c2*r1*r2
            s1[tid][tt] = __float2bfloat16(side ? x : tr);
            s2[tid][tt] = __float2bfloat16(side ? -tr : x);
            t1 += x; t2 += x;                            // then add spike
        }
        __syncthreads();                       // s1/s2 ready for transpose

        const int ksbase = b * 32 + ch * 2;    // global k16-step base of this chunk
        uint4* mat4 = reinterpret_cast<uint4*>(mat);
        #pragma unroll
        for (int it = 0; it < 4; ++it) {
            int f    = it * 128 + tid;         // slot id 0..511
            int lane = f & 31;
            int ksl  = (f >> 5) & 1;
            int frag = f >> 6;                 // 0..7
            int gid  = lane >> 2, tig = lane & 3;
            int pr   = frag * 16 + gid;
            int tb   = ksl * 16 + tig * 2;
            uint4 w1, w2;
            w1.x = *(const uint32_t*)&s1[pr    ][tb    ];
            w1.y = *(const uint32_t*)&s1[pr + 8][tb    ];
            w1.z = *(const uint32_t*)&s1[pr    ][tb + 8];
            w1.w = *(const uint32_t*)&s1[pr + 8][tb + 8];
            w2.x = *(const uint32_t*)&s2[pr    ][tb    ];
            w2.y = *(const uint32_t*)&s2[pr + 8][tb    ];
            w2.z = *(const uint32_t*)&s2[pr    ][tb + 8];
            w2.w = *(const uint32_t*)&s2[pr + 8][tb + 8];
            int ks = ksbase + ksl;
            size_t d16, half;
            if (side == 0) {   // A layout
                d16  = ((size_t)(bx * 2048 + ks) * 8 + frag) * 32 + lane;
                half = 1024ull * 8 * 32;
            } else {           // B layout
                d16  = ((size_t)((bx >> 1) * 2048 + ks) * 16 + (bx & 1) * 8 + frag) * 32 + lane;
                half = 1024ull * 16 * 32;
            }
            mat4[d16]        = w1;
            mat4[d16 + half] = w2;
        }
        __syncthreads();                       // protect s1/s2 reuse
    }
}

// ---------------------------------------------------------------------------
// Kernel 2: bf16 mma.sync GEMM (R5 verbatim, best known). CTA 128x256,
// 8 warps (2Mx4N), warp tile 64x64, split-K=4 -> grid(8,4,4).
// 4-stage cp.async pipeline; wait_group(1) keeps chunks c AND c+1 resident.
// ---------------------------------------------------------------------------
constexpr int      GEMM_STAGES = 4;
constexpr int      CHUNK_U4    = 3072;                       // 1024 A + 2048 B uint4
constexpr uint32_t GEMM_SMEM_B = GEMM_STAGES * CHUNK_U4 * 16; // 196608 B

__global__ void __launch_bounds__(256, 1) stdp_gemm_kernel()
{
    extern __shared__ __align__(16) uint4 sm[];              // [4][3072]
    const int tid  = threadIdx.x;
    const int lane = tid & 31;
    const int wid  = tid >> 5;
    const int wm   = wid & 1;
    const int wn   = wid >> 1;
    const int mt   = blockIdx.x;
    const int nt   = blockIdx.y;
    const int kz   = blockIdx.z;

    const uint4* gA = reinterpret_cast<const uint4*>(g_A)
                    + (size_t)(mt * 2048 + kz * 512) * 8 * 32;
    const uint4* gB = reinterpret_cast<const uint4*>(g_B)
                    + (size_t)(nt * 2048 + kz * 512) * 16 * 32;

    const uint32_t smb = smem_u32(sm);

    auto fill = [&](int c, int s) {
        uint32_t stA = smb + (uint32_t)s * (CHUNK_U4 * 16);
        uint32_t stB = stA + 1024 * 16;
        const uint4* srcA = gA + (size_t)c * 1024;
        const uint4* srcB = gB + (size_t)c * 2048;
        #pragma unroll
        for (int i = 0; i < 4; ++i)
            cp16(stA + (uint32_t)(tid + i * 256) * 16, srcA + tid + i * 256);
        #pragma unroll
        for (int i = 0; i < 8; ++i)
            cp16(stB + (uint32_t)(tid + i * 256) * 16, srcB + tid + i * 256);
    };
    auto aAddr = [&](int c, int ksl, int i) -> const uint4* {
        return sm + (c & 3) * CHUNK_U4 + (size_t)(ksl * 8 + wm * 4 + i) * 32 + lane;
    };
    auto bAddr = [&](int c, int ksl, int j) -> const uint4* {
        return sm + (c & 3) * CHUNK_U4 + 1024 + (size_t)(ksl * 16 + wn * 4 + j) * 32 + lane;
    };

    float acc[4][8][4];
    #pragma unroll
    for (int i = 0; i < 4; ++i)
        #pragma unroll
        for (int j = 0; j < 8; ++j)
            #pragma unroll
            for (int c = 0; c < 4; ++c) acc[i][j][c] = 0.f;

    #pragma unroll
    for (int f = 0; f < 3; ++f) {
        fill(f, f);
        asm volatile("cp.async.commit_group;" ::: "memory");
    }
    asm volatile("cp.async.wait_group 1;" ::: "memory");
    __syncthreads();

    uint4 af[2][4], bf[2][4];
    #pragma unroll
    for (int i = 0; i < 4; ++i) af[0][i] = *aAddr(0, 0, i);
    #pragma unroll
    for (int j = 0; j < 4; ++j) bf[0][j] = *bAddr(0, 0, j);

    for (int c = 0; c < 128; ++c) {
        #pragma unroll
        for (int ksl = 0; ksl < 4; ++ksl) {
            const int cur = ksl & 1;
            const int nxt = cur ^ 1;
            const int pc  = (ksl == 3) ? (c + 1) : c;  // c+1 resident via wait_group(1);
            const int pk  = (ksl + 1) & 3;             // c=127 prefetch dead but safe
            #pragma unroll
            for (int i = 0; i < 4; ++i) af[nxt][i] = *aAddr(pc, pk, i);
            #pragma unroll
            for (int j = 0; j < 4; ++j) bf[nxt][j] = *bAddr(pc, pk, j);
            #pragma unroll
            for (int i = 0; i < 4; ++i) {
                const uint32_t* a = reinterpret_cast<const uint32_t*>(&af[cur][i]);
                #pragma unroll
                for (int j = 0; j < 4; ++j) {
                    mma_bf16(acc[i][2 * j + 0], a, bf[cur][j].x, bf[cur][j].z);
                    mma_bf16(acc[i][2 * j + 1], a, bf[cur][j].y, bf[cur][j].w);
                }
            }
        }
        if (c + 3 < 128) fill(c + 3, (c + 3) & 3);
        asm volatile("cp.async.commit_group;" ::: "memory");
        asm volatile("cp.async.wait_group 1;" ::: "memory");
        __syncthreads();
    }

    const int gid = lane >> 2, tig = lane & 3;
    float* wsbase = g_WS + ((size_t)kz << 20);
    #pragma unroll
    for (int i = 0; i < 4; ++i) {
        int row0 = mt * 128 + (wm * 4 + i) * 16 + gid;
        #pragma unroll
        for (int j = 0; j < 8; ++j) {
            int col = nt * 256 + (wn * 4 + (j >> 1)) * 16 + (j & 1) * 8 + tig * 2;
            float* d0 = wsbase + (size_t)row0 * 1024 + col;
            d0[0] = acc[i][j][0];
            d0[1] = acc[i][j][1];
            float* d1 = d0 + 8 * 1024;
            d1[0] = acc[i][j][2];
            d1[1] = acc[i][j][3];
        }
    }
}

// ---------------------------------------------------------------------------
// Kernel 3: reduce split-K partials + scale 1/(B*T). Deterministic.
// ---------------------------------------------------------------------------
__global__ void __launch_bounds__(256) stdp_reduce_kernel(float* __restrict__ out)
{
    int i = blockIdx.x * 256 + threadIdx.x;
    const float4* w = reinterpret_cast<const float4*>(g_WS);
    float4 a = w[i];
    float4 b = w[i + 262144];
    float4 c = w[i + 524288];
    float4 d = w[i + 786432];
    const float s = 1.0f / 16384.0f;
    float4 r;
    r.x = (a.x + b.x + c.x + d.x) * s;
    r.y = (a.y + b.y + c.y + d.y) * s;
    r.z = (a.z + b.z + c.z + d.z) * s;
    r.w = (a.w + b.w + c.w + d.w) * s;
    reinterpret_cast<float4*>(out)[i] = r;
}

// ---------------------------------------------------------------------------
extern "C" void kernel_launch(void* const* d_in, const int* in_sizes, int n_in,
                              void* d_out, int out_size)
{
    (void)in_sizes; (void)n_in; (void)out_size;
    const float* pre  = (const float*)d_in[0];
    const float* post = (const float*)d_in[1];
    float* out = (float*)d_out;

    stdp_scan_kernel<<<dim3(8, 32, 2), 128>>>(pre, post);

    cudaFuncSetAttribute(stdp_gemm_kernel,
                         cudaFuncAttributeMaxDynamicSharedMemorySize, GEMM_SMEM_B);
    stdp_gemm_kernel<<<dim3(8, 4, 4), 256, GEMM_SMEM_B>>>();

    stdp_reduce_kernel<<<1024, 256>>>(out);
}